// round 4
// baseline (speedup 1.0000x reference)
#include <cuda_runtime.h>

#define Bb 16
#define Ss 4096
#define Hh 1024
#define NN 2048
#define DWw 50
#define OD (Hh + DWw)   // 1074

#define NCH_W 8         // lastw chunks per batch

__device__ float g_last_ctx[Bb * Hh];   // 64KB, stays in L2
__device__ float g_last_w[Bb * 64];
__device__ int   g_start[Bb][NN + 1];

__device__ __forceinline__ void atomicMaxF(float* addr, float val) {
    if (val >= 0.f) atomicMax((int*)addr, __float_as_int(val));
    else            atomicMin((unsigned int*)addr, __float_as_uint(val));
}

__device__ __forceinline__ float4 fmax4(float4 a, float4 b) {
    a.x = fmaxf(a.x, b.x); a.y = fmaxf(a.y, b.y);
    a.z = fmaxf(a.z, b.z); a.w = fmaxf(a.w, b.w);
    return a;
}

// Pass 1: word-span boundaries from sorted seg_ids (int4) + scratch init.
__global__ void prep_kernel(const int* __restrict__ seg) {
    int b = blockIdx.x;
    int i = blockIdx.y * 256 + threadIdx.x;          // int4 index 0..1023
    const int4* s4 = (const int4*)(seg + (long)b * Ss);
    int4 v = s4[i];
    int s = i * 4;
    int prev = (s == 0) ? -1 : __ldg(seg + (long)b * Ss + s - 1);
    if (v.x != prev) g_start[b][v.x] = s;
    if (v.y != v.x)  g_start[b][v.y] = s + 1;
    if (v.z != v.y)  g_start[b][v.z] = s + 2;
    if (v.w != v.z)  g_start[b][v.w] = s + 3;
    if (s + 3 == Ss - 1) g_start[b][v.w + 1] = Ss;   // sentinel end

    if (blockIdx.y == 0) {
        float ninf = __int_as_float(0xFF800000);
        for (int k = threadIdx.x; k < Hh; k += 256) g_last_ctx[b * Hh + k] = ninf;
        if (threadIdx.x < 64) g_last_w[b * 64 + threadIdx.x] = ninf;
    }
}

// Pass 2: per-word segment max + concat. Each block also folds its prefix
// (rows <= ns-2) into g_last_ctx via L2 atomics — ctx is read exactly once.
// lastw reduction rides along in extra blocks.
__global__ void fused_kernel(const float* __restrict__ ctx,
                             const float* __restrict__ wemb,
                             const int* __restrict__ ns_arr,
                             float* __restrict__ out) {
    int bx = blockIdx.x;
    int b  = blockIdx.y;
    int t  = threadIdx.x;            // 0..255
    int ns = ns_arr[b];

    if (bx < NN) {
        int n = bx;
        float* orow = out + ((long)b * NN + n) * OD;
        float2* o2 = (float2*)orow;   // rows 8B-aligned (4296B stride)

        if (n >= ns) {                // padding: zero-fill (out is poisoned)
            for (int i = t; i < OD / 2; i += 256) o2[i] = make_float2(0.f, 0.f);
            return;
        }
        if (n == ns - 1) return;      // written by finish_kernel

        int start = __ldg(&g_start[b][n]);
        int end   = __ldg(&g_start[b][n + 1]);
        int cnt = end - start;
        int k = min(cnt, ns - 1 - start);   // rows counting toward last_ctx

        const float4* crow = (const float4*)(ctx + ((long)b * Ss + start) * Hh);
        float4 acc = crow[t];

        // prefix phase: rows 1..k-1
        int r = 1;
        for (; r < k; r++) acc = fmax4(acc, crow[(long)r * (Hh / 4) + t]);
        float4 accL = acc;

        // remainder phase: rows k..cnt-1 (only last boundary word has both)
        for (; r < cnt; r++) acc = fmax4(acc, crow[(long)r * (Hh / 4) + t]);

        o2[2 * t]     = make_float2(acc.x, acc.y);
        o2[2 * t + 1] = make_float2(acc.z, acc.w);
        if (t < DWw) orow[Hh + t] = wemb[((long)b * NN + n) * DWw + t];

        if (k > 0) {
            float* dst = g_last_ctx + b * Hh + 4 * t;
            atomicMaxF(dst + 0, accL.x);
            atomicMaxF(dst + 1, accL.y);
            atomicMaxF(dst + 2, accL.z);
            atomicMaxF(dst + 3, accL.w);
        }
        return;
    }

    // lastw: max over words 0..ns-1 of word_emb
    int rc = bx - NN;
    if (t >= DWw) return;
    int per = (ns + NCH_W - 1) / NCH_W;
    int r0 = rc * per;
    int r1 = min(ns, r0 + per);
    if (r0 >= r1) return;
    float acc = wemb[((long)b * NN + r0) * DWw + t];
#pragma unroll 4
    for (int r = r0 + 1; r < r1; r++) {
        acc = fmaxf(acc, wemb[((long)b * NN + r) * DWw + t]);
    }
    atomicMaxF(&g_last_w[b * 64 + t], acc);
}

// Pass 3: write the special last-word row from folded scratch.
__global__ void finish_kernel(const int* __restrict__ ns_arr,
                              float* __restrict__ out) {
    int b = blockIdx.x;
    int t = threadIdx.x;
    int n = ns_arr[b] - 1;
    float* orow = out + ((long)b * NN + n) * OD;
    float2* o2 = (float2*)orow;
    float4 v = ((const float4*)(g_last_ctx + b * Hh))[t];
    o2[2 * t]     = make_float2(v.x, v.y);
    o2[2 * t + 1] = make_float2(v.z, v.w);
    if (t < DWw) orow[Hh + t] = g_last_w[b * 64 + t];
}

extern "C" void kernel_launch(void* const* d_in, const int* in_sizes, int n_in,
                              void* d_out, int out_size) {
    const float* ctx  = (const float*)d_in[0];   // [B, S, H]
    const float* wemb = (const float*)d_in[1];   // [B, N, DW]
    const int*   seg  = (const int*)d_in[2];     // [B, S]
    const int*   ns   = (const int*)d_in[3];     // [B]
    float* out = (float*)d_out;                  // [B, N, H+DW]

    prep_kernel<<<dim3(Bb, 4), 256>>>(seg);
    fused_kernel<<<dim3(NN + NCH_W, Bb), 256>>>(ctx, wemb, ns, out);
    finish_kernel<<<Bb, 256>>>(ns, out);
}

// round 5
// speedup vs baseline: 4.7452x; 4.7452x over previous
#include <cuda_runtime.h>

#define Bb 16
#define Ss 4096
#define Hh 1024
#define NN 2048
#define DWw 50
#define OD (Hh + DWw)   // 1074

#define WPB 8                 // words per block
#define NGRP (NN / WPB)       // 256 groups
#define NCH_CTX 64            // lastctx chunks per batch
#define NCH_W 8               // lastw chunks per batch

__device__ float g_last_ctx[Bb * Hh];
__device__ float g_last_w[Bb * 64];
__device__ int   g_start[Bb][NN + 1];

__device__ __forceinline__ void atomicMaxF(float* addr, float val) {
    if (val >= 0.f) atomicMax((int*)addr, __float_as_int(val));
    else            atomicMin((unsigned int*)addr, __float_as_uint(val));
}

__device__ __forceinline__ float4 fmax4(float4 a, float4 b) {
    a.x = fmaxf(a.x, b.x); a.y = fmaxf(a.y, b.y);
    a.z = fmaxf(a.z, b.z); a.w = fmaxf(a.w, b.w);
    return a;
}

// Pass 1: word-span boundaries from sorted seg_ids (int4) + scratch init.
__global__ void prep_kernel(const int* __restrict__ seg) {
    int b = blockIdx.x;
    int i = blockIdx.y * 256 + threadIdx.x;          // int4 index 0..1023
    const int4* s4 = (const int4*)(seg + (long)b * Ss);
    int4 v = s4[i];
    int s = i * 4;
    int prev = (s == 0) ? -1 : __ldg(seg + (long)b * Ss + s - 1);
    if (v.x != prev) g_start[b][v.x] = s;
    if (v.y != v.x)  g_start[b][v.y] = s + 1;
    if (v.z != v.y)  g_start[b][v.z] = s + 2;
    if (v.w != v.z)  g_start[b][v.w] = s + 3;
    if (s + 3 == Ss - 1) g_start[b][v.w + 1] = Ss;   // sentinel end

    if (blockIdx.y == 0) {
        float ninf = __int_as_float(0xFF800000);
        for (int k = threadIdx.x; k < Hh; k += 256) g_last_ctx[b * Hh + k] = ninf;
        if (threadIdx.x < 64) g_last_w[b * 64 + threadIdx.x] = ninf;
    }
}

// Pass 2: 8 consecutive words per block (contiguous ctx streaming) + concat;
// lastctx/lastw chunk reducers in extra blocks overlap the stream.
__global__ void __launch_bounds__(256)
fused_kernel(const float* __restrict__ ctx,
             const float* __restrict__ wemb,
             const int* __restrict__ ns_arr,
             float* __restrict__ out) {
    int bx = blockIdx.x;
    int b  = blockIdx.y;
    int t  = threadIdx.x;            // 0..255, owns channels 4t..4t+3
    int ns = ns_arr[b];

    if (bx < NGRP) {
        int n0 = bx * WPB;
        __shared__ int sbound[WPB + 1];
        if (t <= WPB) sbound[t] = g_start[b][n0 + t];  // entries past ns unused
        __syncthreads();

#pragma unroll
        for (int w = 0; w < WPB; w++) {
            int n = n0 + w;
            float* orow = out + ((long)b * NN + n) * OD;
            float2* o2 = (float2*)orow;   // rows 8B-aligned (4296B stride)

            if (n >= ns) {                // padding: zero-fill (out is poisoned)
                for (int i = t; i < OD / 2; i += 256) o2[i] = make_float2(0.f, 0.f);
                continue;
            }
            if (n == ns - 1) continue;    // written by finish_kernel

            int start = sbound[w];
            int end   = sbound[w + 1];
            const float4* crow = (const float4*)(ctx + ((long)b * Ss + start) * Hh);
            float4 acc = crow[t];
            int cnt = end - start;
#pragma unroll 4
            for (int r = 1; r < cnt; r++) {
                acc = fmax4(acc, crow[(long)r * (Hh / 4) + t]);
            }
            o2[2 * t]     = make_float2(acc.x, acc.y);
            o2[2 * t + 1] = make_float2(acc.z, acc.w);
            if (t < DWw) orow[Hh + t] = wemb[((long)b * NN + n) * DWw + t];
        }
        return;
    }

    int rc = bx - NGRP;
    if (rc < NCH_CTX) {
        // lastctx: max over raw ctx rows 0..ns-2 (chunked, overlapped)
        int rows = ns - 1;
        int per  = (rows + NCH_CTX - 1) / NCH_CTX;
        int r0 = rc * per;
        int r1 = min(rows, r0 + per);
        if (r0 >= r1) return;
        const float4* base = (const float4*)(ctx + ((long)b * Ss + r0) * Hh);
        float4 acc = base[t];
        int cnt = r1 - r0;
#pragma unroll 4
        for (int r = 1; r < cnt; r++) {
            acc = fmax4(acc, base[(long)r * (Hh / 4) + t]);
        }
        float* dst = g_last_ctx + b * Hh + 4 * t;
        atomicMaxF(dst + 0, acc.x);
        atomicMaxF(dst + 1, acc.y);
        atomicMaxF(dst + 2, acc.z);
        atomicMaxF(dst + 3, acc.w);
    } else {
        // lastw: max over words 0..ns-1 of word_emb
        rc -= NCH_CTX;
        if (t >= DWw) return;
        int per = (ns + NCH_W - 1) / NCH_W;
        int r0 = rc * per;
        int r1 = min(ns, r0 + per);
        if (r0 >= r1) return;
        float acc = wemb[((long)b * NN + r0) * DWw + t];
#pragma unroll 4
        for (int r = r0 + 1; r < r1; r++) {
            acc = fmaxf(acc, wemb[((long)b * NN + r) * DWw + t]);
        }
        atomicMaxF(&g_last_w[b * 64 + t], acc);
    }
}

// Pass 3: write the special last-word row from folded scratch.
__global__ void finish_kernel(const int* __restrict__ ns_arr,
                              float* __restrict__ out) {
    int b = blockIdx.x;
    int t = threadIdx.x;
    int n = ns_arr[b] - 1;
    float* orow = out + ((long)b * NN + n) * OD;
    float2* o2 = (float2*)orow;
    float4 v = ((const float4*)(g_last_ctx + b * Hh))[t];
    o2[2 * t]     = make_float2(v.x, v.y);
    o2[2 * t + 1] = make_float2(v.z, v.w);
    if (t < DWw) orow[Hh + t] = g_last_w[b * 64 + t];
}

extern "C" void kernel_launch(void* const* d_in, const int* in_sizes, int n_in,
                              void* d_out, int out_size) {
    const float* ctx  = (const float*)d_in[0];   // [B, S, H]
    const float* wemb = (const float*)d_in[1];   // [B, N, DW]
    const int*   seg  = (const int*)d_in[2];     // [B, S]
    const int*   ns   = (const int*)d_in[3];     // [B]
    float* out = (float*)d_out;                  // [B, N, H+DW]

    prep_kernel<<<dim3(Bb, 4), 256>>>(seg);
    fused_kernel<<<dim3(NGRP + NCH_CTX + NCH_W, Bb), 256>>>(ctx, wemb, ns, out);
    finish_kernel<<<Bb, 256>>>(ns, out);
}

// round 6
// speedup vs baseline: 4.9580x; 1.0448x over previous
#include <cuda_runtime.h>

#define Bb 16
#define Ss 4096
#define Hh 1024
#define NN 2048
#define DWw 50
#define OD (Hh + DWw)   // 1074

#define WPB 16                // words per block
#define NGRP (NN / WPB)       // 128 groups per batch
#define NCH_W 8               // lastw chunks per batch
#define RCH 8                 // reduce chunks per batch (16 groups each)

__device__ float g_part[Bb][NGRP][Hh];   // per-block prefix maxes (8MB)

__device__ __forceinline__ void atomicMaxF(float* addr, float val) {
    if (val >= 0.f) atomicMax((int*)addr, __float_as_int(val));
    else            atomicMin((unsigned int*)addr, __float_as_uint(val));
}

__device__ __forceinline__ float4 fmax4(float4 a, float4 b) {
    a.x = fmaxf(a.x, b.x); a.y = fmaxf(a.y, b.y);
    a.z = fmaxf(a.z, b.z); a.w = fmaxf(a.w, b.w);
    return a;
}

__device__ int g_start[Bb][NN + 1];

// Pass 1: word-span boundaries from sorted seg_ids (int4); init the special
// last-word output row to -inf so later passes can atomic-fold into it.
__global__ void prep_kernel(const int* __restrict__ seg,
                            const int* __restrict__ ns_arr,
                            float* __restrict__ out) {
    int b = blockIdx.x;
    int i = blockIdx.y * 256 + threadIdx.x;          // int4 index 0..1023
    const int4* s4 = (const int4*)(seg + (long)b * Ss);
    int4 v = s4[i];
    int s = i * 4;
    int prev = (s == 0) ? -1 : __ldg(seg + (long)b * Ss + s - 1);
    if (v.x != prev) g_start[b][v.x] = s;
    if (v.y != v.x)  g_start[b][v.y] = s + 1;
    if (v.z != v.y)  g_start[b][v.z] = s + 2;
    if (v.w != v.z)  g_start[b][v.w] = s + 3;
    if (s + 3 == Ss - 1) g_start[b][v.w + 1] = Ss;   // sentinel end

    if (blockIdx.y == 0) {
        float ninf = __int_as_float(0xFF800000);
        int n = ns_arr[b] - 1;
        float* orow = out + ((long)b * NN + n) * OD;
        for (int k = threadIdx.x; k < OD; k += 256) orow[k] = ninf;
    }
}

// Pass 2: 16 consecutive words per block (contiguous ctx streaming) + concat.
// Rows < ns-1 fold into a register blockAcc -> one plain store to g_part
// (zero atomics on the hot path). lastw chunks atomic into the out row's
// word-emb part directly.
__global__ void __launch_bounds__(256)
fused_kernel(const float* __restrict__ ctx,
             const float* __restrict__ wemb,
             const int* __restrict__ ns_arr,
             float* __restrict__ out) {
    int bx = blockIdx.x;
    int b  = blockIdx.y;
    int t  = threadIdx.x;            // 0..255, owns channels 4t..4t+3
    int ns = ns_arr[b];
    float ninf = __int_as_float(0xFF800000);

    if (bx < NGRP) {
        int n0 = bx * WPB;
        __shared__ int sbound[WPB + 1];
        if (t <= WPB) sbound[t] = g_start[b][min(n0 + t, NN)];
        __syncthreads();

        float4 blockAcc = make_float4(ninf, ninf, ninf, ninf);

        for (int w = 0; w < WPB; w++) {
            int n = n0 + w;
            float* orow = out + ((long)b * NN + n) * OD;
            float2* o2 = (float2*)orow;   // rows 8B-aligned (4296B stride)

            if (n >= ns) {                // padding: zero-fill (out is poisoned)
                for (int i = t; i < OD / 2; i += 256) o2[i] = make_float2(0.f, 0.f);
                continue;
            }
            if (n == ns - 1) continue;    // special row: prep init + atomics

            int start = sbound[w];
            int end   = sbound[w + 1];
            int cnt = end - start;
            int k = ns - 1 - start;       // rows of this span counting toward last_ctx
            k = max(0, min(cnt, k));

            const float4* crow = (const float4*)(ctx + ((long)b * Ss + start) * Hh);
            float4 acc = crow[t];
            int r = 1;
            if (k > 0) {
#pragma unroll 4
                for (; r < k; r++) acc = fmax4(acc, crow[(long)r * (Hh / 4) + t]);
                blockAcc = fmax4(blockAcc, acc);
            }
#pragma unroll 4
            for (; r < cnt; r++) acc = fmax4(acc, crow[(long)r * (Hh / 4) + t]);

            o2[2 * t]     = make_float2(acc.x, acc.y);
            o2[2 * t + 1] = make_float2(acc.z, acc.w);
            if (t < DWw) orow[Hh + t] = wemb[((long)b * NN + n) * DWw + t];
        }
        ((float4*)g_part[b][bx])[t] = blockAcc;   // plain store, no atomics
        return;
    }

    // lastw: max over words 0..ns-1 of word_emb, folded straight into out row
    int rc = bx - NGRP;
    if (t >= DWw) return;
    int per = (ns + NCH_W - 1) / NCH_W;
    int r0 = rc * per;
    int r1 = min(ns, r0 + per);
    if (r0 >= r1) return;
    float acc = wemb[((long)b * NN + r0) * DWw + t];
#pragma unroll 4
    for (int r = r0 + 1; r < r1; r++) {
        acc = fmaxf(acc, wemb[((long)b * NN + r) * DWw + t]);
    }
    atomicMaxF(out + ((long)b * NN + ns - 1) * OD + Hh + t, acc);
}

// Pass 3: reduce g_part chunks into the last-word output row's ctx part.
__global__ void reduce_kernel(const int* __restrict__ ns_arr,
                              float* __restrict__ out) {
    int c = blockIdx.x;              // 0..RCH-1
    int b = blockIdx.y;
    int t = threadIdx.x;             // 0..255
    float ninf = __int_as_float(0xFF800000);
    float4 a = make_float4(ninf, ninf, ninf, ninf);
    int g0 = c * (NGRP / RCH);
#pragma unroll 4
    for (int g = g0; g < g0 + NGRP / RCH; g++) {
        a = fmax4(a, ((const float4*)g_part[b][g])[t]);
    }
    int n = ns_arr[b] - 1;
    float* dst = out + ((long)b * NN + n) * OD + 4 * t;
    atomicMaxF(dst + 0, a.x);
    atomicMaxF(dst + 1, a.y);
    atomicMaxF(dst + 2, a.z);
    atomicMaxF(dst + 3, a.w);
}

extern "C" void kernel_launch(void* const* d_in, const int* in_sizes, int n_in,
                              void* d_out, int out_size) {
    const float* ctx  = (const float*)d_in[0];   // [B, S, H]
    const float* wemb = (const float*)d_in[1];   // [B, N, DW]
    const int*   seg  = (const int*)d_in[2];     // [B, S]
    const int*   ns   = (const int*)d_in[3];     // [B]
    float* out = (float*)d_out;                  // [B, N, H+DW]

    prep_kernel<<<dim3(Bb, 4), 256>>>(seg, ns, out);
    fused_kernel<<<dim3(NGRP + NCH_W, Bb), 256>>>(ctx, wemb, ns, out);
    reduce_kernel<<<dim3(RCH, Bb), 256>>>(ns, out);
}